// round 5
// baseline (speedup 1.0000x reference)
#include <cuda_runtime.h>
#include <cuda_bf16.h>
#include <math.h>

// Problem constants
#define Bc   2
#define Qn   4096
#define Kn   4096
#define DQ   512
#define NH   8
#define DH   32
#define INNER (NH*DH)   // 256

// ---------------- scratch (no allocs allowed) ----------------
__device__ float g_qs[Bc*Qn*INNER];   // projected, scaled q  [B,Q,256]
__device__ float g_ks[Bc*Kn*INNER];   // projected k          [B,K,256]
__device__ float g_vs[Bc*Kn*INNER];   // projected v          [B,K,256]
__device__ float g_qo[Bc*Qn*INNER];   // attention out (pre Wo) [B,Q,256]
__device__ float g_m[Bc*NH*Qn];       // row max
__device__ float g_l[Bc*NH*Qn];       // row sum-exp

// ---------------- generic fp32 SGEMM: C = scale*(A@B) + bias ----------------
// A[M,K] row-major, B[K,N] row-major, C[M,N]. Tiles 64x64x16, 256 thr, 4x4/thr.
__global__ void sgemm_kernel(const float* __restrict__ A, const float* __restrict__ B,
                             const float* __restrict__ bias, float* __restrict__ C,
                             int M, int N, int K, float scale) {
    __shared__ float As[16][68];
    __shared__ float Bs[16][64];
    int tid = threadIdx.x;
    int tx = tid & 15, ty = tid >> 4;
    int bm = blockIdx.x * 64, bn = blockIdx.y * 64;

    float acc[4][4];
#pragma unroll
    for (int i = 0; i < 4; i++)
#pragma unroll
        for (int j = 0; j < 4; j++) acc[i][j] = 0.f;

    for (int k0 = 0; k0 < K; k0 += 16) {
        // A tile: 64 rows x 16 cols, one float4 per thread
        {
            int m = tid >> 2, kq = (tid & 3) << 2;
            float4 a = *(const float4*)&A[(size_t)(bm + m) * K + k0 + kq];
            As[kq + 0][m] = a.x; As[kq + 1][m] = a.y;
            As[kq + 2][m] = a.z; As[kq + 3][m] = a.w;
        }
        // B tile: 16 rows x 64 cols
        {
            int kk = tid >> 4, nq = (tid & 15) << 2;
            *(float4*)&Bs[kk][nq] = *(const float4*)&B[(size_t)(k0 + kk) * N + bn + nq];
        }
        __syncthreads();
#pragma unroll
        for (int kk = 0; kk < 16; kk++) {
            float4 a4 = *(const float4*)&As[kk][ty * 4];
            float4 b4 = *(const float4*)&Bs[kk][tx * 4];
            float av[4] = {a4.x, a4.y, a4.z, a4.w};
            float bv[4] = {b4.x, b4.y, b4.z, b4.w};
#pragma unroll
            for (int i = 0; i < 4; i++)
#pragma unroll
                for (int j = 0; j < 4; j++) acc[i][j] += av[i] * bv[j];
        }
        __syncthreads();
    }
#pragma unroll
    for (int i = 0; i < 4; i++) {
        int row = bm + ty * 4 + i;
        int col = bn + tx * 4;
        float4 o;
        o.x = acc[i][0] * scale; o.y = acc[i][1] * scale;
        o.z = acc[i][2] * scale; o.w = acc[i][3] * scale;
        if (bias) {
            o.x += bias[col + 0]; o.y += bias[col + 1];
            o.z += bias[col + 2]; o.w += bias[col + 3];
        }
        *(float4*)&C[(size_t)row * N + col] = o;
    }
}

// ---------------- attention core ----------------
// One block = (b, h, 32 q-rows). 256 threads: thread = (r=tid/8, t=tid%8).
// Streams K in chunks of 64. Writes RAW scores to wraw [B,H,Q,K], keeps
// online (m,l), flash-accumulates PV into g_qo.
__global__ void attn_kernel(const float* __restrict__ qs, const float* __restrict__ ks,
                            const float* __restrict__ vs, float* __restrict__ wraw,
                            float* __restrict__ qo, float* __restrict__ mg,
                            float* __restrict__ lg) {
    int b = blockIdx.z, h = blockIdx.y, q0 = blockIdx.x * 32;
    int tid = threadIdx.x;
    int r = tid >> 3, t = tid & 7;
    int lane = tid & 31, warp = tid >> 5;

    __shared__ float ksm[64][36];
    __shared__ float vsm[64][36];
    __shared__ float psm[32][65];

    // q row -> registers (8 x float4 = 32 floats)
    float4 qreg[8];
    {
        const float* qrow = qs + ((size_t)(b * Qn) + q0 + r) * INNER + h * DH;
#pragma unroll
        for (int i = 0; i < 8; i++) qreg[i] = *(const float4*)(qrow + i * 4);
    }

    float m = -1e30f, l = 0.f;
    float4 o = make_float4(0.f, 0.f, 0.f, 0.f);

    const long wBH = ((long)(b * NH + h)) * Qn;

    for (int c0 = 0; c0 < Kn; c0 += 64) {
        __syncthreads();
        // load 64x32 K and V chunks
#pragma unroll
        for (int i = 0; i < 2; i++) {
            int idx = tid + i * 256;             // 0..511
            int row = idx >> 3, d4 = (idx & 7) << 2;
            size_t gofs = ((size_t)(b * Kn) + c0 + row) * INNER + h * DH + d4;
            *(float4*)&ksm[row][d4] = *(const float4*)&ks[gofs];
            *(float4*)&vsm[row][d4] = *(const float4*)&vs[gofs];
        }
        __syncthreads();

        // scores for this thread's 8 k-indices
        float s[8];
#pragma unroll
        for (int j = 0; j < 8; j++) {
            int kk = t + j * 8;
            float4 a = make_float4(0.f, 0.f, 0.f, 0.f);
#pragma unroll
            for (int i = 0; i < 8; i++) {
                float4 kv = *(const float4*)&ksm[kk][i * 4];
                a.x += qreg[i].x * kv.x; a.y += qreg[i].y * kv.y;
                a.z += qreg[i].z * kv.z; a.w += qreg[i].w * kv.w;
            }
            s[j] = (a.x + a.y) + (a.z + a.w);
            psm[r][kk] = s[j];
        }
        __syncwarp();
        // coalesced flush of raw scores (warp owns rows 4*warp..4*warp+3)
        {
            long base = (wBH + q0 + warp * 4) * (long)Kn + c0;
#pragma unroll
            for (int j = 0; j < 8; j++) {
                int idx = j * 32 + lane;          // 0..255
                int rr = idx >> 6, kk = idx & 63;
                wraw[base + (long)rr * Kn + kk] = psm[warp * 4 + rr][kk];
            }
        }
        __syncwarp();

        // online softmax update (reduce over the row's 8 lanes)
        float smax = s[0];
#pragma unroll
        for (int j = 1; j < 8; j++) smax = fmaxf(smax, s[j]);
#pragma unroll
        for (int off = 4; off; off >>= 1)
            smax = fmaxf(smax, __shfl_xor_sync(0xffffffffu, smax, off));
        float mnew = fmaxf(m, smax);
        float alpha = __expf(m - mnew);
        float psum = 0.f;
#pragma unroll
        for (int j = 0; j < 8; j++) {
            float p = __expf(s[j] - mnew);
            psum += p;
            psm[r][t + j * 8] = p;
        }
#pragma unroll
        for (int off = 4; off; off >>= 1)
            psum += __shfl_xor_sync(0xffffffffu, psum, off);
        l = l * alpha + psum;
        m = mnew;
        o.x *= alpha; o.y *= alpha; o.z *= alpha; o.w *= alpha;
        __syncwarp();

        // PV accumulate: this thread owns dims [t*4, t*4+4)
#pragma unroll 8
        for (int kk = 0; kk < 64; kk++) {
            float p = psm[r][kk];
            float4 v4 = *(const float4*)&vsm[kk][t * 4];
            o.x += p * v4.x; o.y += p * v4.y;
            o.z += p * v4.z; o.w += p * v4.w;
        }
    }

    float inv = 1.f / l;
    float4 of = make_float4(o.x * inv, o.y * inv, o.z * inv, o.w * inv);
    *(float4*)&qo[((size_t)(b * Qn) + q0 + r) * INNER + h * DH + t * 4] = of;
    if (t == 0) {
        int sidx = (int)(wBH + q0 + r);
        mg[sidx] = m;
        lg[sidx] = l;
    }
}

// ---------------- normalize raw scores -> softmax weights ----------------
__global__ void normalize_kernel(float* __restrict__ w, const float* __restrict__ mg,
                                 const float* __restrict__ lg, long n4) {
    long idx4 = (long)blockIdx.x * blockDim.x + threadIdx.x;
    if (idx4 >= n4) return;
    int row = (int)(idx4 >> 10);   // 1024 float4 per K-row of 4096
    float m = mg[row];
    float inv = 1.f / lg[row];
    float4 s4 = *(float4*)&w[idx4 * 4];
    s4.x = __expf(s4.x - m) * inv;
    s4.y = __expf(s4.y - m) * inv;
    s4.z = __expf(s4.z - m) * inv;
    s4.w = __expf(s4.w - m) * inv;
    *(float4*)&w[idx4 * 4] = s4;
}

// ---------------- launch ----------------
extern "C" void kernel_launch(void* const* d_in, const int* in_sizes, int n_in,
                              void* d_out, int out_size) {
    const float* query = (const float*)d_in[0];
    const float* key   = (const float*)d_in[1];
    const float* value = (const float*)d_in[2];
    const float* Wq    = (const float*)d_in[3];
    const float* Wk    = (const float*)d_in[4];
    const float* Wv    = (const float*)d_in[5];
    const float* Wo    = (const float*)d_in[6];
    const float* bo    = (const float*)d_in[7];

    float* out_attn = (float*)d_out;                       // [B,Q,512]
    float* out_w    = (float*)d_out + (size_t)Bc*Qn*DQ;    // [B,H,Q,K]

    float *qs, *ksp, *vsp, *qop, *mp, *lp;
    cudaGetSymbolAddress((void**)&qs,  g_qs);
    cudaGetSymbolAddress((void**)&ksp, g_ks);
    cudaGetSymbolAddress((void**)&vsp, g_vs);
    cudaGetSymbolAddress((void**)&qop, g_qo);
    cudaGetSymbolAddress((void**)&mp,  g_m);
    cudaGetSymbolAddress((void**)&lp,  g_l);

    const int M = Bc * Qn;          // 8192
    const float scaling = 0.17677669529663687f;  // 1/sqrt(32)

    // 1) projections
    {
        dim3 grid(M / 64, INNER / 64);
        sgemm_kernel<<<grid, 256>>>(query, Wq, nullptr, qs,  M, INNER, DQ, scaling);
        sgemm_kernel<<<grid, 256>>>(key,   Wk, nullptr, ksp, M, INNER, DQ, 1.f);
        sgemm_kernel<<<grid, 256>>>(value, Wv, nullptr, vsp, M, INNER, DQ, 1.f);
    }
    // 2) attention core (raw scores + flash PV)
    {
        dim3 grid(Qn / 32, NH, Bc);
        attn_kernel<<<grid, 256>>>(qs, ksp, vsp, out_w, qop, mp, lp);
    }
    // 3) normalize weights in place
    {
        long n4 = (long)Bc * NH * Qn * Kn / 4;   // 67,108,864
        int threads = 256;
        long blocks = (n4 + threads - 1) / threads;
        normalize_kernel<<<(unsigned)blocks, threads>>>(out_w, mp, lp, n4);
    }
    // 4) output projection + bias
    {
        dim3 grid(M / 64, DQ / 64);
        sgemm_kernel<<<grid, 256>>>(qop, Wo, bo, out_attn, M, DQ, INNER, 1.f);
    }
}

// round 6
// speedup vs baseline: 1.6876x; 1.6876x over previous
#include <cuda_runtime.h>
#include <cuda_bf16.h>
#include <math.h>

// Problem constants
#define Bc   2
#define Qn   4096
#define Kn   4096
#define DQ   512
#define NH   8
#define DH   32
#define INNER (NH*DH)   // 256

// ---------------- scratch (no allocs allowed) ----------------
__device__ float g_qs[Bc*Qn*INNER];   // projected, scaled q  [B,Q,256]
__device__ float g_ks[Bc*Kn*INNER];   // projected k          [B,K,256]
__device__ float g_vs[Bc*Kn*INNER];   // projected v          [B,K,256]
__device__ float g_qo[Bc*Qn*INNER];   // attention out (pre Wo) [B,Q,256]
__device__ float g_m[Bc*NH*Qn];       // row max
__device__ float g_l[Bc*NH*Qn];       // row sum-exp

// ---------------- packed f32x2 helpers (sm_100+) ----------------
typedef unsigned long long ull;

__device__ __forceinline__ ull pack2(float x, float y) {
    ull r;
    asm("mov.b64 %0, {%1, %2};" : "=l"(r) : "f"(x), "f"(y));
    return r;
}
__device__ __forceinline__ void unpack2(ull v, float &x, float &y) {
    asm("mov.b64 {%0, %1}, %2;" : "=f"(x), "=f"(y) : "l"(v));
}
__device__ __forceinline__ void ffma2(ull &d, ull a, ull b) {
    asm("fma.rn.f32x2 %0, %1, %2, %0;" : "+l"(d) : "l"(a), "l"(b));
}
__device__ __forceinline__ void fmul2(ull &d, ull a) {
    asm("mul.rn.f32x2 %0, %0, %1;" : "+l"(d) : "l"(a));
}
__device__ __forceinline__ void fadd2(ull &d, ull a) {
    asm("add.rn.f32x2 %0, %0, %1;" : "+l"(d) : "l"(a));
}

// ---------------- generic fp32 SGEMM: C = scale*(A@B) + bias ----------------
__global__ void sgemm_kernel(const float* __restrict__ A, const float* __restrict__ B,
                             const float* __restrict__ bias, float* __restrict__ C,
                             int M, int N, int K, float scale) {
    __shared__ float As[16][68];
    __shared__ float Bs[16][64];
    int tid = threadIdx.x;
    int tx = tid & 15, ty = tid >> 4;
    int bm = blockIdx.x * 64, bn = blockIdx.y * 64;

    float acc[4][4];
#pragma unroll
    for (int i = 0; i < 4; i++)
#pragma unroll
        for (int j = 0; j < 4; j++) acc[i][j] = 0.f;

    for (int k0 = 0; k0 < K; k0 += 16) {
        {
            int m = tid >> 2, kq = (tid & 3) << 2;
            float4 a = *(const float4*)&A[(size_t)(bm + m) * K + k0 + kq];
            As[kq + 0][m] = a.x; As[kq + 1][m] = a.y;
            As[kq + 2][m] = a.z; As[kq + 3][m] = a.w;
        }
        {
            int kk = tid >> 4, nq = (tid & 15) << 2;
            *(float4*)&Bs[kk][nq] = *(const float4*)&B[(size_t)(k0 + kk) * N + bn + nq];
        }
        __syncthreads();
#pragma unroll
        for (int kk = 0; kk < 16; kk++) {
            float4 a4 = *(const float4*)&As[kk][ty * 4];
            float4 b4 = *(const float4*)&Bs[kk][tx * 4];
            float av[4] = {a4.x, a4.y, a4.z, a4.w};
            float bv[4] = {b4.x, b4.y, b4.z, b4.w};
#pragma unroll
            for (int i = 0; i < 4; i++)
#pragma unroll
                for (int j = 0; j < 4; j++) acc[i][j] += av[i] * bv[j];
        }
        __syncthreads();
    }
#pragma unroll
    for (int i = 0; i < 4; i++) {
        int row = bm + ty * 4 + i;
        int col = bn + tx * 4;
        float4 o;
        o.x = acc[i][0] * scale; o.y = acc[i][1] * scale;
        o.z = acc[i][2] * scale; o.w = acc[i][3] * scale;
        if (bias) {
            o.x += bias[col + 0]; o.y += bias[col + 1];
            o.z += bias[col + 2]; o.w += bias[col + 3];
        }
        *(float4*)&C[(size_t)row * N + col] = o;
    }
}

// ---------------- attention core, 128q x 128k tiles, f32x2 ----------------
// grid = (Qn/128, NH, Bc), 256 threads.
// Score phase: thread (ty=tid/16, tx=tid%16) owns 8 rows x 8 cols, packed
// accumulators (row-pairs). PV phase: thread (half=tid/128, rgrp, dgrp) owns
// 8 rows x 4 dims over half the kk range; halves reduced at block end.
//
// smem carve (floats):
#define OFF_Q 0            // qsm[32][132]  (kd-major, transposed)
#define OFF_K 4224         // ksm[32][132]
#define OFF_V 8448         // vsm[128][36]
#define OFF_P 13056        // pt [128][132] (kk-major, rows swizzled per 4-block)
#define OFF_A 29952        // alpha[128]
#define OFF_L 30080        // l[128]
#define SMEM_FLOATS 30208
#define SMEM_BYTES (SMEM_FLOATS*4)

__global__ void attn_kernel(const float* __restrict__ qs, const float* __restrict__ ks,
                            const float* __restrict__ vs, float* __restrict__ wraw,
                            float* __restrict__ qo, float* __restrict__ mg,
                            float* __restrict__ lg) {
    extern __shared__ float sm[];
    float* qsm   = sm + OFF_Q;
    float* ksm   = sm + OFF_K;
    float* vsm   = sm + OFF_V;
    float* pt    = sm + OFF_P;
    float* alsm  = sm + OFF_A;
    float* lsm   = sm + OFF_L;

    const int b = blockIdx.z, h = blockIdx.y, q0 = blockIdx.x * 128;
    const int tid = threadIdx.x;
    const int ty = tid >> 4, tx = tid & 15;
    const int tt = tid & 127, half = tid >> 7;
    const int rgrp = tt >> 3, dgrp = tt & 7;
    const size_t bh = (size_t)(b * NH + h);

    // ---- load Q tile transposed: qsm[kd][row] ----
    {
        int row = tid >> 1, hf = tid & 1;
        const float* gq = qs + ((size_t)(b * Qn) + q0 + row) * INNER + h * DH + hf * 16;
#pragma unroll
        for (int i = 0; i < 4; i++) {
            float4 v = *(const float4*)(gq + i * 4);
            int kd = hf * 16 + i * 4;
            qsm[(kd + 0) * 132 + row] = v.x;
            qsm[(kd + 1) * 132 + row] = v.y;
            qsm[(kd + 2) * 132 + row] = v.z;
            qsm[(kd + 3) * 132 + row] = v.w;
        }
    }

    float mrow[8], lrow[8];
#pragma unroll
    for (int i = 0; i < 8; i++) { mrow[i] = -1e30f; lrow[i] = 0.f; }

    ull oacc[4][4];
#pragma unroll
    for (int ip = 0; ip < 4; ip++)
#pragma unroll
        for (int j = 0; j < 4; j++) oacc[ip][j] = 0ull;

    for (int c0 = 0; c0 < Kn; c0 += 128) {
        __syncthreads();   // prev PV done; safe to overwrite ksm/vsm/pt

        // ---- load K chunk transposed: ksm[kd][col] ----
        {
            int col = tid >> 1, hf = tid & 1;
            const float* gk = ks + ((size_t)(b * Kn) + c0 + col) * INNER + h * DH + hf * 16;
#pragma unroll
            for (int i = 0; i < 4; i++) {
                float4 v = *(const float4*)(gk + i * 4);
                int kd = hf * 16 + i * 4;
                ksm[(kd + 0) * 132 + col] = v.x;
                ksm[(kd + 1) * 132 + col] = v.y;
                ksm[(kd + 2) * 132 + col] = v.z;
                ksm[(kd + 3) * 132 + col] = v.w;
            }
        }
        // ---- load V chunk: vsm[kk][d] ----
        {
#pragma unroll
            for (int i = 0; i < 4; i++) {
                int f = tid + i * 256;
                int kk = f >> 3, d4 = (f & 7) << 2;
                *(float4*)&vsm[kk * 36 + d4] =
                    *(const float4*)(vs + ((size_t)(b * Kn) + c0 + kk) * INNER + h * DH + d4);
            }
        }
        __syncthreads();

        // ---- score GEMM: 8x8 per thread, packed row-pairs ----
        ull acc[4][8];
#pragma unroll
        for (int ip = 0; ip < 4; ip++)
#pragma unroll
            for (int j = 0; j < 8; j++) acc[ip][j] = 0ull;

#pragma unroll 4
        for (int kd = 0; kd < 32; kd++) {
            const ulonglong2* ap = (const ulonglong2*)&qsm[kd * 132 + ty * 8];
            ulonglong2 a01 = ap[0], a23 = ap[1];
            ull a2[4] = {a01.x, a01.y, a23.x, a23.y};
            float4 b0 = *(const float4*)&ksm[kd * 132 + tx * 8];
            float4 b1 = *(const float4*)&ksm[kd * 132 + tx * 8 + 4];
            ull bb[8];
            bb[0] = pack2(b0.x, b0.x); bb[1] = pack2(b0.y, b0.y);
            bb[2] = pack2(b0.z, b0.z); bb[3] = pack2(b0.w, b0.w);
            bb[4] = pack2(b1.x, b1.x); bb[5] = pack2(b1.y, b1.y);
            bb[6] = pack2(b1.z, b1.z); bb[7] = pack2(b1.w, b1.w);
#pragma unroll
            for (int ip = 0; ip < 4; ip++)
#pragma unroll
                for (int j = 0; j < 8; j++) ffma2(acc[ip][j], a2[ip], bb[j]);
        }

        // ---- unpack scores ----
        float sc[8][8];
#pragma unroll
        for (int ip = 0; ip < 4; ip++)
#pragma unroll
            for (int j = 0; j < 8; j++)
                unpack2(acc[ip][j], sc[2 * ip][j], sc[2 * ip + 1][j]);

        // ---- write raw scores (coalesced) ----
        {
            size_t wbase = (bh * Qn + q0 + ty * 8) * (size_t)Kn + c0 + tx * 8;
#pragma unroll
            for (int i = 0; i < 8; i++) {
                *(float4*)&wraw[wbase + (size_t)i * Kn] =
                    make_float4(sc[i][0], sc[i][1], sc[i][2], sc[i][3]);
                *(float4*)&wraw[wbase + (size_t)i * Kn + 4] =
                    make_float4(sc[i][4], sc[i][5], sc[i][6], sc[i][7]);
            }
        }

        // ---- online softmax (reduce across the 16 tx lanes of each row) ----
        float alpha_loc[8];
#pragma unroll
        for (int i = 0; i < 8; i++) {
            float rmax = sc[i][0];
#pragma unroll
            for (int j = 1; j < 8; j++) rmax = fmaxf(rmax, sc[i][j]);
#pragma unroll
            for (int off = 8; off; off >>= 1)
                rmax = fmaxf(rmax, __shfl_xor_sync(0xffffffffu, rmax, off));
            float mnew = fmaxf(mrow[i], rmax);
            float al = __expf(mrow[i] - mnew);
            float ps = 0.f;
#pragma unroll
            for (int j = 0; j < 8; j++) {
                sc[i][j] = __expf(sc[i][j] - mnew);
                ps += sc[i][j];
            }
#pragma unroll
            for (int off = 8; off; off >>= 1)
                ps += __shfl_xor_sync(0xffffffffu, ps, off);
            lrow[i] = lrow[i] * al + ps;
            mrow[i] = mnew;
            alpha_loc[i] = al;
        }
        if (tx == 0) {
#pragma unroll
            for (int i = 0; i < 8; i++) alsm[ty * 8 + i] = alpha_loc[i];
        }

        // ---- store P to pt[kk][row] with 4-row-block swizzle ----
#pragma unroll
        for (int j = 0; j < 8; j++) {
            int kk = tx * 8 + j;
            int sw = tx & 7;
            float* bp = &pt[kk * 132];
            *(float4*)&bp[((ty * 2) ^ sw) * 4] =
                make_float4(sc[0][j], sc[1][j], sc[2][j], sc[3][j]);
            *(float4*)&bp[((ty * 2 + 1) ^ sw) * 4] =
                make_float4(sc[4][j], sc[5][j], sc[6][j], sc[7][j]);
        }
        __syncthreads();

        // ---- PV: rescale then accumulate over this half's kk range ----
#pragma unroll
        for (int ip = 0; ip < 4; ip++) {
            ull al2 = *(const ull*)&alsm[rgrp * 8 + ip * 2];
#pragma unroll
            for (int j = 0; j < 4; j++) fmul2(oacc[ip][j], al2);
        }
        {
            int kb = half * 64;
#pragma unroll 2
            for (int k2 = 0; k2 < 64; k2++) {
                int kk = kb + k2;
                int sw = (kk >> 3) & 7;
                const ulonglong2* pp = (const ulonglong2*)&pt[kk * 132];
                ulonglong2 pa = pp[(rgrp * 2) ^ sw];
                ulonglong2 pb = pp[(rgrp * 2 + 1) ^ sw];
                ull p2[4] = {pa.x, pa.y, pb.x, pb.y};
                float4 v4 = *(const float4*)&vsm[kk * 36 + dgrp * 4];
                ull vv[4] = {pack2(v4.x, v4.x), pack2(v4.y, v4.y),
                             pack2(v4.z, v4.z), pack2(v4.w, v4.w)};
#pragma unroll
                for (int ip = 0; ip < 4; ip++)
#pragma unroll
                    for (int j = 0; j < 4; j++) ffma2(oacc[ip][j], p2[ip], vv[j]);
            }
        }
    }

    // ---- finalize: stats out, combine halves, normalize, write O ----
    if (tx == 0) {
#pragma unroll
        for (int i = 0; i < 8; i++) {
            int row = ty * 8 + i;
            lsm[row] = lrow[i];
            size_t gi = bh * Qn + q0 + row;
            mg[gi] = mrow[i];
            lg[gi] = lrow[i];
        }
    }
    __syncthreads();
    ull* red = (ull*)pt;
    if (half == 1) {
#pragma unroll
        for (int ip = 0; ip < 4; ip++)
#pragma unroll
            for (int j = 0; j < 4; j++) red[tt * 16 + ip * 4 + j] = oacc[ip][j];
    }
    __syncthreads();
    if (half == 0) {
#pragma unroll
        for (int ip = 0; ip < 4; ip++)
#pragma unroll
            for (int j = 0; j < 4; j++) fadd2(oacc[ip][j], red[tt * 16 + ip * 4 + j]);
#pragma unroll
        for (int ip = 0; ip < 4; ip++) {
            float f0[4], f1[4];
#pragma unroll
            for (int j = 0; j < 4; j++) unpack2(oacc[ip][j], f0[j], f1[j]);
            int r0 = rgrp * 8 + ip * 2;
            float inv0 = 1.0f / lsm[r0];
            float inv1 = 1.0f / lsm[r0 + 1];
            *(float4*)&qo[((size_t)(b * Qn) + q0 + r0) * INNER + h * DH + dgrp * 4] =
                make_float4(f0[0] * inv0, f0[1] * inv0, f0[2] * inv0, f0[3] * inv0);
            *(float4*)&qo[((size_t)(b * Qn) + q0 + r0 + 1) * INNER + h * DH + dgrp * 4] =
                make_float4(f1[0] * inv1, f1[1] * inv1, f1[2] * inv1, f1[3] * inv1);
        }
    }
}

// ---------------- normalize raw scores -> softmax weights ----------------
__global__ void normalize_kernel(float* __restrict__ w, const float* __restrict__ mg,
                                 const float* __restrict__ lg, long n4) {
    long idx4 = (long)blockIdx.x * blockDim.x + threadIdx.x;
    if (idx4 >= n4) return;
    int row = (int)(idx4 >> 10);   // 1024 float4 per K-row of 4096
    float m = mg[row];
    float inv = 1.f / lg[row];
    float4 s4 = *(float4*)&w[idx4 * 4];
    s4.x = __expf(s4.x - m) * inv;
    s4.y = __expf(s4.y - m) * inv;
    s4.z = __expf(s4.z - m) * inv;
    s4.w = __expf(s4.w - m) * inv;
    *(float4*)&w[idx4 * 4] = s4;
}

// ---------------- launch ----------------
extern "C" void kernel_launch(void* const* d_in, const int* in_sizes, int n_in,
                              void* d_out, int out_size) {
    const float* query = (const float*)d_in[0];
    const float* key   = (const float*)d_in[1];
    const float* value = (const float*)d_in[2];
    const float* Wq    = (const float*)d_in[3];
    const float* Wk    = (const float*)d_in[4];
    const float* Wv    = (const float*)d_in[5];
    const float* Wo    = (const float*)d_in[6];
    const float* bo    = (const float*)d_in[7];

    float* out_attn = (float*)d_out;                       // [B,Q,512]
    float* out_w    = (float*)d_out + (size_t)Bc*Qn*DQ;    // [B,H,Q,K]

    float *qs, *ksp, *vsp, *qop, *mp, *lp;
    cudaGetSymbolAddress((void**)&qs,  g_qs);
    cudaGetSymbolAddress((void**)&ksp, g_ks);
    cudaGetSymbolAddress((void**)&vsp, g_vs);
    cudaGetSymbolAddress((void**)&qop, g_qo);
    cudaGetSymbolAddress((void**)&mp,  g_m);
    cudaGetSymbolAddress((void**)&lp,  g_l);

    const int M = Bc * Qn;          // 8192
    const float scaling = 0.17677669529663687f;  // 1/sqrt(32)

    // 1) projections
    {
        dim3 grid(M / 64, INNER / 64);
        sgemm_kernel<<<grid, 256>>>(query, Wq, nullptr, qs,  M, INNER, DQ, scaling);
        sgemm_kernel<<<grid, 256>>>(key,   Wk, nullptr, ksp, M, INNER, DQ, 1.f);
        sgemm_kernel<<<grid, 256>>>(value, Wv, nullptr, vsp, M, INNER, DQ, 1.f);
    }
    // 2) attention core (raw scores + flash PV), 128-row tiles
    {
        cudaFuncSetAttribute(attn_kernel, cudaFuncAttributeMaxDynamicSharedMemorySize,
                             SMEM_BYTES);
        dim3 grid(Qn / 128, NH, Bc);
        attn_kernel<<<grid, 256, SMEM_BYTES>>>(qs, ksp, vsp, out_w, qop, mp, lp);
    }
    // 3) normalize weights in place
    {
        long n4 = (long)Bc * NH * Qn * Kn / 4;   // 67,108,864
        int threads = 256;
        long blocks = (n4 + threads - 1) / threads;
        normalize_kernel<<<(unsigned)blocks, threads>>>(out_w, mp, lp, n4);
    }
    // 4) output projection + bias
    {
        dim3 grid(M / 64, DQ / 64);
        sgemm_kernel<<<grid, 256>>>(qop, Wo, bo, out_attn, M, DQ, INNER, 1.f);
    }
}

// round 8
// speedup vs baseline: 1.7295x; 1.0248x over previous
#include <cuda_runtime.h>
#include <cuda_bf16.h>
#include <math.h>

// Problem constants
#define Bc   2
#define Qn   4096
#define Kn   4096
#define DQ   512
#define NH   8
#define DH   32
#define INNER (NH*DH)   // 256

// ---------------- scratch (no allocs allowed) ----------------
__device__ float g_qs[Bc*Qn*INNER];   // projected, scaled q  [B,Q,256]
__device__ float g_ks[Bc*Kn*INNER];   // projected k          [B,K,256]
__device__ float g_vs[Bc*Kn*INNER];   // projected v          [B,K,256]
__device__ float g_qo[Bc*Qn*INNER];   // attention out (pre Wo) [B,Q,256]
__device__ float g_m[Bc*NH*Qn];       // row max
__device__ float g_l[Bc*NH*Qn];       // row sum-exp

// ---------------- packed f32x2 helpers (sm_100+) ----------------
typedef unsigned long long ull;

__device__ __forceinline__ ull pack2(float x, float y) {
    ull r;
    asm("mov.b64 %0, {%1, %2};" : "=l"(r) : "f"(x), "f"(y));
    return r;
}
__device__ __forceinline__ void unpack2(ull v, float &x, float &y) {
    asm("mov.b64 {%0, %1}, %2;" : "=f"(x), "=f"(y) : "l"(v));
}
__device__ __forceinline__ void ffma2(ull &d, ull a, ull b) {
    asm("fma.rn.f32x2 %0, %1, %2, %0;" : "+l"(d) : "l"(a), "l"(b));
}
__device__ __forceinline__ void fmul2(ull &d, ull a) {
    asm("mul.rn.f32x2 %0, %0, %1;" : "+l"(d) : "l"(a));
}
__device__ __forceinline__ void fadd2(ull &d, ull a) {
    asm("add.rn.f32x2 %0, %0, %1;" : "+l"(d) : "l"(a));
}

// ---------------- generic fp32 SGEMM: C = scale*(A@B) + bias ----------------
__global__ void sgemm_kernel(const float* __restrict__ A, const float* __restrict__ B,
                             const float* __restrict__ bias, float* __restrict__ C,
                             int M, int N, int K, float scale) {
    __shared__ float As[16][68];
    __shared__ float Bs[16][64];
    int tid = threadIdx.x;
    int tx = tid & 15, ty = tid >> 4;
    int bm = blockIdx.x * 64, bn = blockIdx.y * 64;

    float acc[4][4];
#pragma unroll
    for (int i = 0; i < 4; i++)
#pragma unroll
        for (int j = 0; j < 4; j++) acc[i][j] = 0.f;

    for (int k0 = 0; k0 < K; k0 += 16) {
        {
            int m = tid >> 2, kq = (tid & 3) << 2;
            float4 a = *(const float4*)&A[(size_t)(bm + m) * K + k0 + kq];
            As[kq + 0][m] = a.x; As[kq + 1][m] = a.y;
            As[kq + 2][m] = a.z; As[kq + 3][m] = a.w;
        }
        {
            int kk = tid >> 4, nq = (tid & 15) << 2;
            *(float4*)&Bs[kk][nq] = *(const float4*)&B[(size_t)(k0 + kk) * N + bn + nq];
        }
        __syncthreads();
#pragma unroll
        for (int kk = 0; kk < 16; kk++) {
            float4 a4 = *(const float4*)&As[kk][ty * 4];
            float4 b4 = *(const float4*)&Bs[kk][tx * 4];
            float av[4] = {a4.x, a4.y, a4.z, a4.w};
            float bv[4] = {b4.x, b4.y, b4.z, b4.w};
#pragma unroll
            for (int i = 0; i < 4; i++)
#pragma unroll
                for (int j = 0; j < 4; j++) acc[i][j] += av[i] * bv[j];
        }
        __syncthreads();
    }
#pragma unroll
    for (int i = 0; i < 4; i++) {
        int row = bm + ty * 4 + i;
        int col = bn + tx * 4;
        float4 o;
        o.x = acc[i][0] * scale; o.y = acc[i][1] * scale;
        o.z = acc[i][2] * scale; o.w = acc[i][3] * scale;
        if (bias) {
            o.x += bias[col + 0]; o.y += bias[col + 1];
            o.z += bias[col + 2]; o.w += bias[col + 3];
        }
        *(float4*)&C[(size_t)row * N + col] = o;
    }
}

// ---------------- attention core, 128q x 128k tiles, f32x2 ----------------
// grid = (Qn/128, NH, Bc), 256 threads, 2 CTAs/SM target.
// Score phase: two passes of 4 rows (regs <=128). Thread (ty,tx) owns rows
// ty*8+rp*4.. and cols tx*8.. PV: halves over kk with block-end reduction.
//
// smem carve (floats):
#define OFF_Q 0            // qsm[32][128]  (kd-major, transposed)
#define OFF_K 4096         // ksm[32][128]
#define OFF_V 8192         // vsm[128][32]
#define OFF_P 12288        // pt [128][128] (kk-major, row-quads XOR-swizzled)
#define OFF_A 28672        // alpha[128]
#define OFF_L 28800        // l[128]
#define SMEM_FLOATS 28928
#define SMEM_BYTES (SMEM_FLOATS*4)   // 115712 B

__global__ void __launch_bounds__(256, 2)
attn_kernel(const float* __restrict__ qs, const float* __restrict__ ks,
            const float* __restrict__ vs, float* __restrict__ wraw,
            float* __restrict__ qo, float* __restrict__ mg,
            float* __restrict__ lg) {
    extern __shared__ float sm[];
    float* qsm   = sm + OFF_Q;
    float* ksm   = sm + OFF_K;
    float* vsm   = sm + OFF_V;
    float* pt    = sm + OFF_P;
    float* alsm  = sm + OFF_A;
    float* lsm   = sm + OFF_L;

    const int b = blockIdx.z, h = blockIdx.y, q0 = blockIdx.x * 128;
    const int tid = threadIdx.x;
    const int ty = tid >> 4, tx = tid & 15;
    const int tt = tid & 127, half = tid >> 7;
    const int rgrp = tt >> 3, dgrp = tt & 7;
    const size_t bh = (size_t)(b * NH + h);

    // ---- load Q tile transposed: qsm[kd][row] ----
    {
        int row = tid >> 1, hf = tid & 1;
        const float* gq = qs + ((size_t)(b * Qn) + q0 + row) * INNER + h * DH + hf * 16;
#pragma unroll
        for (int i = 0; i < 4; i++) {
            float4 v = *(const float4*)(gq + i * 4);
            int kd = hf * 16 + i * 4;
            qsm[(kd + 0) * 128 + row] = v.x;
            qsm[(kd + 1) * 128 + row] = v.y;
            qsm[(kd + 2) * 128 + row] = v.z;
            qsm[(kd + 3) * 128 + row] = v.w;
        }
    }

    float mrow[8], lrow[8];
#pragma unroll
    for (int i = 0; i < 8; i++) { mrow[i] = -1e30f; lrow[i] = 0.f; }

    ull oacc[4][4];
#pragma unroll
    for (int ip = 0; ip < 4; ip++)
#pragma unroll
        for (int j = 0; j < 4; j++) oacc[ip][j] = 0ull;

    for (int c0 = 0; c0 < Kn; c0 += 128) {
        __syncthreads();   // prev PV done; safe to overwrite ksm/vsm/pt

        // ---- load K chunk transposed: ksm[kd][col] ----
        {
            int col = tid >> 1, hf = tid & 1;
            const float* gk = ks + ((size_t)(b * Kn) + c0 + col) * INNER + h * DH + hf * 16;
#pragma unroll
            for (int i = 0; i < 4; i++) {
                float4 v = *(const float4*)(gk + i * 4);
                int kd = hf * 16 + i * 4;
                ksm[(kd + 0) * 128 + col] = v.x;
                ksm[(kd + 1) * 128 + col] = v.y;
                ksm[(kd + 2) * 128 + col] = v.z;
                ksm[(kd + 3) * 128 + col] = v.w;
            }
        }
        // ---- load V chunk: vsm[kk][d] ----
        {
#pragma unroll
            for (int i = 0; i < 4; i++) {
                int f = tid + i * 256;
                int kk = f >> 3, d4 = (f & 7) << 2;
                *(float4*)&vsm[kk * 32 + d4] =
                    *(const float4*)(vs + ((size_t)(b * Kn) + c0 + kk) * INNER + h * DH + d4);
            }
        }
        __syncthreads();

        // ---- score GEMM in two 4-row passes (keeps regs <= 128) ----
#pragma unroll
        for (int rp = 0; rp < 2; rp++) {
            const int r0 = ty * 8 + rp * 4;      // first row of this pass

            // acc[row i][col-pair jp], cols native-paired from ksm
            ull acc[4][4];
#pragma unroll
            for (int i = 0; i < 4; i++)
#pragma unroll
                for (int jp = 0; jp < 4; jp++) acc[i][jp] = 0ull;

#pragma unroll 4
            for (int kd = 0; kd < 32; kd++) {
                float4 a4 = *(const float4*)&qsm[kd * 128 + r0];
                ull aa[4] = {pack2(a4.x, a4.x), pack2(a4.y, a4.y),
                             pack2(a4.z, a4.z), pack2(a4.w, a4.w)};
                const ulonglong2* bp = (const ulonglong2*)&ksm[kd * 128 + tx * 8];
                ulonglong2 b01 = bp[0], b23 = bp[1];
                ull bb[4] = {b01.x, b01.y, b23.x, b23.y};
#pragma unroll
                for (int i = 0; i < 4; i++)
#pragma unroll
                    for (int jp = 0; jp < 4; jp++) ffma2(acc[i][jp], aa[i], bb[jp]);
            }

            // unpack scores
            float sc[4][8];
#pragma unroll
            for (int i = 0; i < 4; i++)
#pragma unroll
                for (int jp = 0; jp < 4; jp++)
                    unpack2(acc[i][jp], sc[i][2 * jp], sc[i][2 * jp + 1]);

            // write raw scores (coalesced float4 pairs)
            {
                size_t wbase = (bh * Qn + q0 + r0) * (size_t)Kn + c0 + tx * 8;
#pragma unroll
                for (int i = 0; i < 4; i++) {
                    *(float4*)&wraw[wbase + (size_t)i * Kn] =
                        make_float4(sc[i][0], sc[i][1], sc[i][2], sc[i][3]);
                    *(float4*)&wraw[wbase + (size_t)i * Kn + 4] =
                        make_float4(sc[i][4], sc[i][5], sc[i][6], sc[i][7]);
                }
            }

            // online softmax for these 4 rows
#pragma unroll
            for (int i = 0; i < 4; i++) {
                const int ri = rp * 4 + i;
                float rmax = sc[i][0];
#pragma unroll
                for (int j = 1; j < 8; j++) rmax = fmaxf(rmax, sc[i][j]);
#pragma unroll
                for (int off = 8; off; off >>= 1)
                    rmax = fmaxf(rmax, __shfl_xor_sync(0xffffffffu, rmax, off));
                float mnew = fmaxf(mrow[ri], rmax);
                float al = __expf(mrow[ri] - mnew);
                float ps = 0.f;
#pragma unroll
                for (int j = 0; j < 8; j++) {
                    sc[i][j] = __expf(sc[i][j] - mnew);
                    ps += sc[i][j];
                }
#pragma unroll
                for (int off = 8; off; off >>= 1)
                    ps += __shfl_xor_sync(0xffffffffu, ps, off);
                lrow[ri] = lrow[ri] * al + ps;
                mrow[ri] = mnew;
                if (tx == 0) alsm[ty * 8 + ri] = al;
            }

            // store P to pt[kk][row-quad], XOR-swizzled
            {
                const int quad = ty * 2 + rp;    // 0..31
#pragma unroll
                for (int j = 0; j < 8; j++) {
                    int kk = tx * 8 + j;
                    int sw = tx & 7;
                    *(float4*)&pt[kk * 128 + ((quad ^ sw) << 2)] =
                        make_float4(sc[0][j], sc[1][j], sc[2][j], sc[3][j]);
                }
            }
        }
        __syncthreads();

        // ---- PV: rescale then accumulate over this half's kk range ----
#pragma unroll
        for (int ip = 0; ip < 4; ip++) {
            ull al2 = *(const ull*)&alsm[rgrp * 8 + ip * 2];
#pragma unroll
            for (int j = 0; j < 4; j++) fmul2(oacc[ip][j], al2);
        }
        {
            int kb = half * 64;
#pragma unroll 2
            for (int k2 = 0; k2 < 64; k2++) {
                int kk = kb + k2;
                int sw = (kk >> 3) & 7;
                const ulonglong2* pp = (const ulonglong2*)&pt[kk * 128];
                ulonglong2 pa = pp[(rgrp * 2) ^ sw];
                ulonglong2 pb = pp[(rgrp * 2 + 1) ^ sw];
                ull p2[4] = {pa.x, pa.y, pb.x, pb.y};
                float4 v4 = *(const float4*)&vsm[kk * 32 + dgrp * 4];
                ull vv[4] = {pack2(v4.x, v4.x), pack2(v4.y, v4.y),
                             pack2(v4.z, v4.z), pack2(v4.w, v4.w)};
#pragma unroll
                for (int ip = 0; ip < 4; ip++)
#pragma unroll
                    for (int j = 0; j < 4; j++) ffma2(oacc[ip][j], p2[ip], vv[j]);
            }
        }
    }

    // ---- finalize: stats out, combine halves, normalize, write O ----
    if (tx == 0) {
#pragma unroll
        for (int i = 0; i < 8; i++) {
            int row = ty * 8 + i;
            lsm[row] = lrow[i];
            size_t gi = bh * Qn + q0 + row;
            mg[gi] = mrow[i];
            lg[gi] = lrow[i];
        }
    }
    __syncthreads();
    ull* red = (ull*)pt;
    if (half == 1) {
#pragma unroll
        for (int ip = 0; ip < 4; ip++)
#pragma unroll
            for (int j = 0; j < 4; j++) red[tt * 16 + ip * 4 + j] = oacc[ip][j];
    }
    __syncthreads();
    if (half == 0) {
#pragma unroll
        for (int ip = 0; ip < 4; ip++)
#pragma unroll
            for (int j = 0; j < 4; j++) fadd2(oacc[ip][j], red[tt * 16 + ip * 4 + j]);
#pragma unroll
        for (int ip = 0; ip < 4; ip++) {
            float f0[4], f1[4];
#pragma unroll
            for (int j = 0; j < 4; j++) unpack2(oacc[ip][j], f0[j], f1[j]);
            int r0 = rgrp * 8 + ip * 2;
            float inv0 = 1.0f / lsm[r0];
            float inv1 = 1.0f / lsm[r0 + 1];
            *(float4*)&qo[((size_t)(b * Qn) + q0 + r0) * INNER + h * DH + dgrp * 4] =
                make_float4(f0[0] * inv0, f0[1] * inv0, f0[2] * inv0, f0[3] * inv0);
            *(float4*)&qo[((size_t)(b * Qn) + q0 + r0 + 1) * INNER + h * DH + dgrp * 4] =
                make_float4(f1[0] * inv1, f1[1] * inv1, f1[2] * inv1, f1[3] * inv1);
        }
    }
}

// ---------------- normalize raw scores -> softmax weights ----------------
__global__ void normalize_kernel(float* __restrict__ w, const float* __restrict__ mg,
                                 const float* __restrict__ lg, long n4) {
    long idx4 = (long)blockIdx.x * blockDim.x + threadIdx.x;
    if (idx4 >= n4) return;
    int row = (int)(idx4 >> 10);   // 1024 float4 per K-row of 4096
    float m = mg[row];
    float inv = 1.f / lg[row];
    float4 s4 = *(float4*)&w[idx4 * 4];
    s4.x = __expf(s4.x - m) * inv;
    s4.y = __expf(s4.y - m) * inv;
    s4.z = __expf(s4.z - m) * inv;
    s4.w = __expf(s4.w - m) * inv;
    *(float4*)&w[idx4 * 4] = s4;
}

// ---------------- launch ----------------
extern "C" void kernel_launch(void* const* d_in, const int* in_sizes, int n_in,
                              void* d_out, int out_size) {
    const float* query = (const float*)d_in[0];
    const float* key   = (const float*)d_in[1];
    const float* value = (const float*)d_in[2];
    const float* Wq    = (const float*)d_in[3];
    const float* Wk    = (const float*)d_in[4];
    const float* Wv    = (const float*)d_in[5];
    const float* Wo    = (const float*)d_in[6];
    const float* bo    = (const float*)d_in[7];

    float* out_attn = (float*)d_out;                       // [B,Q,512]
    float* out_w    = (float*)d_out + (size_t)Bc*Qn*DQ;    // [B,H,Q,K]

    float *qs, *ksp, *vsp, *qop, *mp, *lp;
    cudaGetSymbolAddress((void**)&qs,  g_qs);
    cudaGetSymbolAddress((void**)&ksp, g_ks);
    cudaGetSymbolAddress((void**)&vsp, g_vs);
    cudaGetSymbolAddress((void**)&qop, g_qo);
    cudaGetSymbolAddress((void**)&mp,  g_m);
    cudaGetSymbolAddress((void**)&lp,  g_l);

    const int M = Bc * Qn;          // 8192
    const float scaling = 0.17677669529663687f;  // 1/sqrt(32)

    // 1) projections
    {
        dim3 grid(M / 64, INNER / 64);
        sgemm_kernel<<<grid, 256>>>(query, Wq, nullptr, qs,  M, INNER, DQ, scaling);
        sgemm_kernel<<<grid, 256>>>(key,   Wk, nullptr, ksp, M, INNER, DQ, 1.f);
        sgemm_kernel<<<grid, 256>>>(value, Wv, nullptr, vsp, M, INNER, DQ, 1.f);
    }
    // 2) attention core (raw scores + flash PV), 128-row tiles
    {
        cudaFuncSetAttribute(attn_kernel, cudaFuncAttributeMaxDynamicSharedMemorySize,
                             SMEM_BYTES);
        dim3 grid(Qn / 128, NH, Bc);
        attn_kernel<<<grid, 256, SMEM_BYTES>>>(qs, ksp, vsp, out_w, qop, mp, lp);
    }
    // 3) normalize weights in place
    {
        long n4 = (long)Bc * NH * Qn * Kn / 4;   // 67,108,864
        int threads = 256;
        long blocks = (n4 + threads - 1) / threads;
        normalize_kernel<<<(unsigned)blocks, threads>>>(out_w, mp, lp, n4);
    }
    // 4) output projection + bias
    {
        dim3 grid(M / 64, DQ / 64);
        sgemm_kernel<<<grid, 256>>>(qop, Wo, bo, out_attn, M, DQ, INNER, 1.f);
    }
}